// round 11
// baseline (speedup 1.0000x reference)
#include <cuda_runtime.h>
#include <math.h>

#define H 1536
#define HK 8
#define HV 16
#define DK 64
#define DV 64
#define KEY_DIM 512
#define VALUE_DIM 1024
#define CONV_DIM 2048
#define NROWS (CONV_DIM + VALUE_DIM + 2*HV)   // 3104
#define K2B 384                               // kernel-2 blocks, 4 rows each

__device__ __align__(16) float g_qkv[CONV_DIM];
__device__ __align__(16) float g_z[VALUE_DIM];
__device__ __align__(16) float g_ab[2*HV];
__device__ __align__(16) float g_outf[VALUE_DIM];
__device__ volatile int g_c2;   // delta-done counter (16)
__device__ int g_c3;            // completion counter -> resets g_c2

__device__ __forceinline__ float warp_sum(float v) {
#pragma unroll
    for (int o = 16; o > 0; o >>= 1) v += __shfl_xor_sync(0xffffffffu, v, o);
    return v;
}
__device__ __forceinline__ void cp16(void* s, const void* g) {
    unsigned sa = (unsigned)__cvta_generic_to_shared(s);
    asm volatile("cp.async.cg.shared.global [%0], [%1], 16;\n" :: "r"(sa), "l"(g));
}
__device__ __forceinline__ void cp_commit() { asm volatile("cp.async.commit_group;\n"); }
__device__ __forceinline__ void cp_wait0()  { asm volatile("cp.async.wait_group 0;\n" ::: "memory"); }

// ---------------- Kernel A: fused input GEMVs (pure R5 shape) ----------------
// 776 blocks, 2 warps/row, 4 rows/block, 6 front-batched float4 loads per warp.
__global__ __launch_bounds__(256) void gemv_in(
    const float* __restrict__ x,
    const float* __restrict__ Wqkv, const float* __restrict__ Wz,
    const float* __restrict__ Wa,   const float* __restrict__ Wb)
{
    __shared__ __align__(16) float sx[H];
    __shared__ float part[8];
    const int tid = threadIdx.x;
#pragma unroll
    for (int i = tid; i < H / 4; i += 256)
        ((float4*)sx)[i] = ((const float4*)x)[i];
    __syncthreads();

    const int lane = tid & 31;
    const int wid  = tid >> 5;
    const int row  = blockIdx.x * 4 + (wid >> 1);
    const int half = wid & 1;

    const float* w;
    if (row < CONV_DIM)                         w = Wqkv + (size_t)row * H;
    else if (row < CONV_DIM + VALUE_DIM)        w = Wz + (size_t)(row - CONV_DIM) * H;
    else if (row < CONV_DIM + VALUE_DIM + HV)   w = Wa + (size_t)(row - CONV_DIM - VALUE_DIM) * H;
    else                                        w = Wb + (size_t)(row - CONV_DIM - VALUE_DIM - HV) * H;

    const float4* w4 = (const float4*)w + half * 192 + lane;
    const float4* s4 = (const float4*)sx + half * 192 + lane;

    float4 a0 = w4[0],  a1 = w4[32], a2 = w4[64],
           a3 = w4[96], a4 = w4[128], a5 = w4[160];
    float4 b0 = s4[0],  b1 = s4[32], b2 = s4[64],
           b3 = s4[96], b4 = s4[128], b5 = s4[160];

    float acc = a0.x*b0.x + a0.y*b0.y + a0.z*b0.z + a0.w*b0.w;
    acc += a1.x*b1.x + a1.y*b1.y + a1.z*b1.z + a1.w*b1.w;
    acc += a2.x*b2.x + a2.y*b2.y + a2.z*b2.z + a2.w*b2.w;
    acc += a3.x*b3.x + a3.y*b3.y + a3.z*b3.z + a3.w*b3.w;
    acc += a4.x*b4.x + a4.y*b4.y + a4.z*b4.z + a4.w*b4.w;
    acc += a5.x*b5.x + a5.y*b5.y + a5.z*b5.z + a5.w*b5.w;

    acc = warp_sum(acc);
    if (lane == 0) part[wid] = acc;
    __syncthreads();

    if (tid < 4) {
        const int r = blockIdx.x * 4 + tid;
        float v = part[2*tid] + part[2*tid + 1];
        if (r < CONV_DIM)                        g_qkv[r] = v;
        else if (r < CONV_DIM + VALUE_DIM)       g_z[r - CONV_DIM] = v;
        else if (r < CONV_DIM + VALUE_DIM + HV)  g_ab[r - CONV_DIM - VALUE_DIM] = v;
        else                                     g_ab[HV + r - CONV_DIM - VALUE_DIM - HV] = v;
    }
}

// -------- Kernel B: delta (blocks 0..15) + gemv_out (all 384 blocks) ---------
// Each block streams its 4 W_out rows (16KB) to smem via cp.async at t=0
// (delta blocks: right after releasing the flag); blocks >=16 spin on the
// 16-count flag BEHIND their in-flight cp.asyncs, so the wait is hidden.
__global__ __launch_bounds__(256) void delta_out(
    const float* __restrict__ convw, const float* __restrict__ Alog,
    const float* __restrict__ dtb,   const float* __restrict__ nw,
    const float* __restrict__ state, const float* __restrict__ cache,
    const float* __restrict__ Wout,  float* __restrict__ y)
{
    __shared__ __align__(16) float sw[4 * VALUE_DIM];   // 16KB W_out tile
    __shared__ __align__(16) float so[VALUE_DIM];       // o_final
    __shared__ float part[8];
    __shared__ float sq[DK], sk[DK], sv[DV];
    __shared__ float s_qs, s_ks, s_qk, s_eg, s_beta, s_rms;
    __shared__ float r_part[256], o_part[256];

    const int tid  = threadIdx.x;
    const int lane = tid & 31;
    const int wid  = tid >> 5;
    const int b    = blockIdx.x;
    const float* wsrc = Wout + (size_t)b * 4 * VALUE_DIM;

    if (b >= HV) {
        // stream W_out tile first, then hide the spin behind it
#pragma unroll
        for (int c = 0; c < 4; ++c)
            cp16(&sw[(c * 256 + tid) * 4], wsrc + (c * 256 + tid) * 4);
        cp_commit();
        if (tid == 0) { while (g_c2 != HV) __nanosleep(32); }
        __syncthreads();
        __threadfence();
    } else {
        // ---- delta rule for head b ----
        const int h = b, kh = h >> 1;
        if (tid < 192) {
            int ch;
            if (tid < 64)       ch = kh * 64 + tid;
            else if (tid < 128) ch = KEY_DIM + kh * 64 + (tid - 64);
            else                ch = 2 * KEY_DIM + h * 64 + (tid - 128);
            float co = g_qkv[ch]         * convw[ch * 4 + 3]
                     + cache[ch * 3 + 0] * convw[ch * 4 + 0]
                     + cache[ch * 3 + 1] * convw[ch * 4 + 1]
                     + cache[ch * 3 + 2] * convw[ch * 4 + 2];
            co = co / (1.f + expf(-co));  // silu
            if (tid < 64)       sq[tid] = co;
            else if (tid < 128) sk[tid - 64] = co;
            else                sv[tid - 128] = co;
        }
        __syncthreads();

        if (wid == 0) {
            float a = sq[lane], c2 = sq[lane + 32];
            float s = warp_sum(a * a + c2 * c2);
            if (lane == 0) s_qs = rsqrtf(s + 1e-12f) * 0.125f;  // * Dk^-0.5
        } else if (wid == 1) {
            float a = sk[lane], c2 = sk[lane + 32];
            float s = warp_sum(a * a + c2 * c2);
            if (lane == 0) s_ks = rsqrtf(s + 1e-12f);
        } else if (wid == 2) {
            float s = warp_sum(sq[lane]*sk[lane] + sq[lane+32]*sk[lane+32]);
            if (lane == 0) s_qk = s;
        } else if (wid == 3 && lane == 0) {
            float aa = g_ab[h] + dtb[h];
            float sp = (aa > 20.f) ? aa : log1pf(expf(aa));      // softplus
            s_eg = expf(-expf(Alog[h]) * sp);                    // exp(g)
            s_beta = 1.f / (1.f + expf(-g_ab[HV + h]));          // sigmoid
        }
        __syncthreads();

        const float qk = s_qk * s_qs * s_ks;
        if (tid < 64)       sq[tid]      *= s_qs;
        else if (tid < 128) sk[tid - 64] *= s_ks;
        __syncthreads();

        const int v  = tid & 63;
        const int kq = tid >> 6;
        const float* st = state + (size_t)h * DK * DV;
        float ar = 0.f, ao = 0.f;
#pragma unroll
        for (int kk = 0; kk < 16; ++kk) {
            int k = kq * 16 + kk;
            float s = st[k * DV + v];
            ar += s * sk[k];
            ao += s * sq[k];
        }
        r_part[tid] = ar; o_part[tid] = ao;
        __syncthreads();

        if (tid < 64) {
            float r0 = r_part[v] + r_part[64+v] + r_part[128+v] + r_part[192+v];
            float o0 = o_part[v] + o_part[64+v] + o_part[128+v] + o_part[192+v];
            float delta = (sv[v] - s_eg * r0) * s_beta;
            float out   = s_eg * o0 + qk * delta;
            r_part[v] = out * out;
            o_part[v] = out;
        }
        __syncthreads();
        if (wid == 0) {
            float s = warp_sum(r_part[lane] + r_part[lane + 32]);
            if (lane == 0) s_rms = rsqrtf(s * (1.f / 64.f) + 1e-6f);
        }
        __syncthreads();
        if (tid < 64) {
            float zg  = g_z[h * 64 + v];
            float sil = zg / (1.f + expf(-zg));
            __stcg(&g_outf[h * 64 + v], nw[v] * o_part[v] * s_rms * sil);
        }
        __threadfence();
        __syncthreads();
        if (tid == 0) atomicAdd((int*)&g_c2, 1);   // release ASAP

        // now stream this block's W_out tile
#pragma unroll
        for (int c = 0; c < 4; ++c)
            cp16(&sw[(c * 256 + tid) * 4], wsrc + (c * 256 + tid) * 4);
        cp_commit();
        if (tid == 0) { while (g_c2 != HV) __nanosleep(32); }
        __syncthreads();
        __threadfence();
    }

    // ---- common: y[b*4 .. b*4+3] = W_out rows @ o_final ----
    for (int i = tid; i < VALUE_DIM; i += 256)
        so[i] = __ldcg(&g_outf[i]);
    cp_wait0();
    __syncthreads();

    {
        const int r    = wid >> 1;          // local row 0..3
        const int half = wid & 1;
        const float4* w4 = (const float4*)sw + r * 256 + half * 128 + lane;
        const float4* s4 = (const float4*)so + half * 128 + lane;

        float4 a0 = w4[0], a1 = w4[32], a2 = w4[64], a3 = w4[96];
        float4 b0 = s4[0], b1 = s4[32], b2 = s4[64], b3 = s4[96];

        float acc = a0.x*b0.x + a0.y*b0.y + a0.z*b0.z + a0.w*b0.w;
        acc += a1.x*b1.x + a1.y*b1.y + a1.z*b1.z + a1.w*b1.w;
        acc += a2.x*b2.x + a2.y*b2.y + a2.z*b2.z + a2.w*b2.w;
        acc += a3.x*b3.x + a3.y*b3.y + a3.z*b3.z + a3.w*b3.w;

        acc = warp_sum(acc);
        if (lane == 0) part[wid] = acc;
    }
    __syncthreads();
    if (tid < 4) y[b * 4 + tid] = part[2*tid] + part[2*tid + 1];

    // reset for next graph replay (all blocks observed g_c2==HV before here)
    if (tid == 0) {
        int t = atomicAdd(&g_c3, 1);
        if (t == K2B - 1) { g_c3 = 0; g_c2 = 0; }
    }
}

extern "C" void kernel_launch(void* const* d_in, const int* in_sizes, int n_in,
                              void* d_out, int out_size)
{
    const float* x     = (const float*)d_in[0];
    const float* Wqkv  = (const float*)d_in[1];
    const float* Wz    = (const float*)d_in[2];
    const float* Wa    = (const float*)d_in[3];
    const float* Wb    = (const float*)d_in[4];
    const float* Wout  = (const float*)d_in[5];
    const float* convw = (const float*)d_in[6];
    const float* Alog  = (const float*)d_in[7];
    const float* dtb   = (const float*)d_in[8];
    const float* nw    = (const float*)d_in[9];
    const float* state = (const float*)d_in[10];
    const float* cache = (const float*)d_in[11];
    float* y = (float*)d_out;

    gemv_in<<<NROWS / 4, 256>>>(x, Wqkv, Wz, Wa, Wb);
    delta_out<<<K2B, 256>>>(convw, Alog, dtb, nw, state, cache, Wout, y);
}

// round 16
// speedup vs baseline: 1.1600x; 1.1600x over previous
#include <cuda_runtime.h>
#include <math.h>

#define H 1536
#define HK 8
#define HV 16
#define DK 64
#define DV 64
#define KEY_DIM 512
#define VALUE_DIM 1024
#define CONV_DIM 2048
#define NROWS (CONV_DIM + VALUE_DIM + 2*HV)   // 3104

__device__ __align__(16) float g_qkv[CONV_DIM];
__device__ __align__(16) float g_z[VALUE_DIM];
__device__ __align__(16) float g_ab[2*HV];
__device__ __align__(16) float g_outf[VALUE_DIM];

__device__ __forceinline__ float warp_sum(float v) {
#pragma unroll
    for (int o = 16; o > 0; o >>= 1) v += __shfl_xor_sync(0xffffffffu, v, o);
    return v;
}

__device__ __forceinline__ void l2_prefetch(const void* g, unsigned bytes) {
    asm volatile("cp.async.bulk.prefetch.L2.global [%0], %1;" :: "l"(g), "r"(bytes));
}

// ---------------- Kernel A: fused input GEMVs (R5 shape) + L2 prefetch -------
// 776 blocks, 2 warps/row, 4 rows/block, 6 front-batched float4 loads per warp.
// Blocks 0..95 prefetch W_out (6MB), 96..111 state (256KB), 112/113 convw/cache
// into L2; lines persist across launch boundaries (L2 not flushed per launch).
__global__ __launch_bounds__(256) void gemv_in(
    const float* __restrict__ x,
    const float* __restrict__ Wqkv, const float* __restrict__ Wz,
    const float* __restrict__ Wa,   const float* __restrict__ Wb,
    const float* __restrict__ Wout, const float* __restrict__ state,
    const float* __restrict__ convw, const float* __restrict__ cache)
{
    __shared__ __align__(16) float sx[H];
    __shared__ float part[8];
    const int tid = threadIdx.x;
    const int b   = blockIdx.x;

    // L2 prefetch of later-kernel data (measured ~free in this kernel)
    if (b < 96) {
        if (tid < 16)
            l2_prefetch((const char*)Wout + (size_t)b * 65536 + tid * 4096, 4096);
    } else if (b < 112) {
        if (tid < 4)
            l2_prefetch((const char*)state + (size_t)(b - 96) * 16384 + tid * 4096, 4096);
    } else if (b == 112) {
        if (tid < 8)
            l2_prefetch((const char*)convw + tid * 4096, 4096);   // 32KB conv weights
    } else if (b == 113) {
        if (tid < 6)
            l2_prefetch((const char*)cache + tid * 4096, 4096);   // 24KB conv cache
    }

#pragma unroll
    for (int i = tid; i < H / 4; i += 256)
        ((float4*)sx)[i] = ((const float4*)x)[i];
    __syncthreads();

    const int lane = tid & 31;
    const int wid  = tid >> 5;
    const int row  = b * 4 + (wid >> 1);
    const int half = wid & 1;

    const float* w;
    if (row < CONV_DIM)                         w = Wqkv + (size_t)row * H;
    else if (row < CONV_DIM + VALUE_DIM)        w = Wz + (size_t)(row - CONV_DIM) * H;
    else if (row < CONV_DIM + VALUE_DIM + HV)   w = Wa + (size_t)(row - CONV_DIM - VALUE_DIM) * H;
    else                                        w = Wb + (size_t)(row - CONV_DIM - VALUE_DIM - HV) * H;

    const float4* w4 = (const float4*)w + half * 192 + lane;
    const float4* s4 = (const float4*)sx + half * 192 + lane;

    float4 a0 = w4[0],  a1 = w4[32], a2 = w4[64],
           a3 = w4[96], a4 = w4[128], a5 = w4[160];   // front-batched
    float4 b0 = s4[0],  b1 = s4[32], b2 = s4[64],
           b3 = s4[96], b4 = s4[128], b5 = s4[160];

    float acc = a0.x*b0.x + a0.y*b0.y + a0.z*b0.z + a0.w*b0.w;
    acc += a1.x*b1.x + a1.y*b1.y + a1.z*b1.z + a1.w*b1.w;
    acc += a2.x*b2.x + a2.y*b2.y + a2.z*b2.z + a2.w*b2.w;
    acc += a3.x*b3.x + a3.y*b3.y + a3.z*b3.z + a3.w*b3.w;
    acc += a4.x*b4.x + a4.y*b4.y + a4.z*b4.z + a4.w*b4.w;
    acc += a5.x*b5.x + a5.y*b5.y + a5.z*b5.z + a5.w*b5.w;

    acc = warp_sum(acc);
    if (lane == 0) part[wid] = acc;
    __syncthreads();

    if (tid < 4) {
        const int r = b * 4 + tid;
        float v = part[2*tid] + part[2*tid + 1];
        if (r < CONV_DIM)                        g_qkv[r] = v;
        else if (r < CONV_DIM + VALUE_DIM)       g_z[r - CONV_DIM] = v;
        else if (r < CONV_DIM + VALUE_DIM + HV)  g_ab[r - CONV_DIM - VALUE_DIM] = v;
        else                                     g_ab[HV + r - CONV_DIM - VALUE_DIM - HV] = v;
    }
}

// ------------- Kernel B: conv + l2norm + delta rule + gated RMSNorm ----------
__global__ __launch_bounds__(256) void delta_kernel(
    const float* __restrict__ convw, const float* __restrict__ Alog,
    const float* __restrict__ dtb,   const float* __restrict__ nw,
    const float* __restrict__ state, const float* __restrict__ cache)
{
    const int h   = blockIdx.x;       // value head 0..15
    const int kh  = h >> 1;
    const int tid = threadIdx.x;
    const int lane = tid & 31, wid = tid >> 5;

    __shared__ float sq[DK], sk[DK], sv[DV];
    __shared__ float s_qs, s_ks, s_qk, s_eg, s_beta, s_rms;
    __shared__ float r_part[256], o_part[256];

    if (tid < 192) {
        int ch;
        if (tid < 64)       ch = kh * 64 + tid;
        else if (tid < 128) ch = KEY_DIM + kh * 64 + (tid - 64);
        else                ch = 2 * KEY_DIM + h * 64 + (tid - 128);
        float co = g_qkv[ch]         * convw[ch * 4 + 3]
                 + cache[ch * 3 + 0] * convw[ch * 4 + 0]
                 + cache[ch * 3 + 1] * convw[ch * 4 + 1]
                 + cache[ch * 3 + 2] * convw[ch * 4 + 2];
        co = co / (1.f + expf(-co));  // silu
        if (tid < 64)       sq[tid] = co;
        else if (tid < 128) sk[tid - 64] = co;
        else                sv[tid - 128] = co;
    }
    __syncthreads();

    if (wid == 0) {
        float a = sq[lane], b2 = sq[lane + 32];
        float s = warp_sum(a * a + b2 * b2);
        if (lane == 0) s_qs = rsqrtf(s + 1e-12f) * 0.125f;  // * Dk^-0.5
    } else if (wid == 1) {
        float a = sk[lane], b2 = sk[lane + 32];
        float s = warp_sum(a * a + b2 * b2);
        if (lane == 0) s_ks = rsqrtf(s + 1e-12f);
    } else if (wid == 2) {
        float s = warp_sum(sq[lane] * sk[lane] + sq[lane + 32] * sk[lane + 32]);
        if (lane == 0) s_qk = s;
    } else if (wid == 3 && lane == 0) {
        float aa = g_ab[h] + dtb[h];
        float sp = (aa > 20.f) ? aa : log1pf(expf(aa));      // softplus
        s_eg = expf(-expf(Alog[h]) * sp);                    // exp(g)
        s_beta = 1.f / (1.f + expf(-g_ab[HV + h]));          // sigmoid
    }
    __syncthreads();

    const float qk = s_qk * s_qs * s_ks;

    if (tid < 64)       sq[tid]      *= s_qs;
    else if (tid < 128) sk[tid - 64] *= s_ks;
    __syncthreads();

    const int v  = tid & 63;
    const int kq = tid >> 6;
    const float* st = state + (size_t)h * DK * DV;   // L2-warm (prefetched)
    float ar = 0.f, ao = 0.f;
#pragma unroll
    for (int kk = 0; kk < 16; ++kk) {
        int k = kq * 16 + kk;
        float s = st[k * DV + v];
        ar += s * sk[k];
        ao += s * sq[k];
    }
    r_part[tid] = ar; o_part[tid] = ao;
    __syncthreads();

    if (tid < 64) {
        float r0 = r_part[v] + r_part[64 + v] + r_part[128 + v] + r_part[192 + v];
        float o0 = o_part[v] + o_part[64 + v] + o_part[128 + v] + o_part[192 + v];
        float delta = (sv[v] - s_eg * r0) * s_beta;
        float out   = s_eg * o0 + qk * delta;
        r_part[v] = out * out;
        o_part[v] = out;
    }
    __syncthreads();
    if (wid == 0) {
        float s = warp_sum(r_part[lane] + r_part[lane + 32]);
        if (lane == 0) s_rms = rsqrtf(s * (1.f / 64.f) + 1e-6f);
    }
    __syncthreads();
    if (tid < 64) {
        float zg  = g_z[h * 64 + v];
        float sil = zg / (1.f + expf(-zg));
        g_outf[h * 64 + v] = nw[v] * o_part[v] * s_rms * sil;
    }
}

// ---------------- Kernel C: y = W_out @ out_final (R5 shape) -----------------
// 384 blocks, 2 warps/row, 4 rows/block, 4 front-batched float4 loads per warp.
__global__ __launch_bounds__(256) void gemv_out(
    const float* __restrict__ Wout, float* __restrict__ y)
{
    __shared__ __align__(16) float so[VALUE_DIM];
    __shared__ float part[8];
    const int tid = threadIdx.x;
#pragma unroll
    for (int i = tid; i < VALUE_DIM / 4; i += 256)
        ((float4*)so)[i] = ((const float4*)g_outf)[i];
    __syncthreads();

    const int lane = tid & 31;
    const int wid  = tid >> 5;
    const int row  = blockIdx.x * 4 + (wid >> 1);
    const int half = wid & 1;

    const float4* w4 = (const float4*)(Wout + (size_t)row * VALUE_DIM) + half * 128 + lane;
    const float4* s4 = (const float4*)so + half * 128 + lane;

    float4 a0 = w4[0], a1 = w4[32], a2 = w4[64], a3 = w4[96];
    float4 b0 = s4[0], b1 = s4[32], b2 = s4[64], b3 = s4[96];

    float acc = a0.x*b0.x + a0.y*b0.y + a0.z*b0.z + a0.w*b0.w;
    acc += a1.x*b1.x + a1.y*b1.y + a1.z*b1.z + a1.w*b1.w;
    acc += a2.x*b2.x + a2.y*b2.y + a2.z*b2.z + a2.w*b2.w;
    acc += a3.x*b3.x + a3.y*b3.y + a3.z*b3.z + a3.w*b3.w;

    acc = warp_sum(acc);
    if (lane == 0) part[wid] = acc;
    __syncthreads();
    if (tid < 4) y[blockIdx.x * 4 + tid] = part[2*tid] + part[2*tid + 1];
}

extern "C" void kernel_launch(void* const* d_in, const int* in_sizes, int n_in,
                              void* d_out, int out_size)
{
    const float* x     = (const float*)d_in[0];
    const float* Wqkv  = (const float*)d_in[1];
    const float* Wz    = (const float*)d_in[2];
    const float* Wa    = (const float*)d_in[3];
    const float* Wb    = (const float*)d_in[4];
    const float* Wout  = (const float*)d_in[5];
    const float* convw = (const float*)d_in[6];
    const float* Alog  = (const float*)d_in[7];
    const float* dtb   = (const float*)d_in[8];
    const float* nw    = (const float*)d_in[9];
    const float* state = (const float*)d_in[10];
    const float* cache = (const float*)d_in[11];
    float* y = (float*)d_out;

    gemv_in<<<NROWS / 4, 256>>>(x, Wqkv, Wz, Wa, Wb, Wout, state, convw, cache);
    delta_kernel<<<HV, 256>>>(convw, Alog, dtb, nw, state, cache);
    gemv_out<<<H / 4, 256>>>(Wout, y);
}